// round 1
// baseline (speedup 1.0000x reference)
#include <cuda_runtime.h>
#include <cstdint>
#include <math_constants.h>

#define BATCH 16
#define NPRED 1024
#define NGT   1024
#define NP1   1025
#define NCLS  3

// Output layout (float32, flattened tuple):
// [0]=closs, [1]=mloss, [2]=semloss,
// [3 .. 3+16*1025*1025) = matches_gt,
// then 16*3*1024 = semantics_gt
#define M_BASE   3
#define SG_BASE  (3 + BATCH * NP1 * NP1)

// Scratch (no allocs allowed -> __device__ globals)
__device__ uint32_t g_keys[BATCH * NPRED];
__device__ float g_closs[BATCH * 8];
__device__ float g_semloss[BATCH * 8];
__device__ float g_mloss[BATCH];

// ---------------------------------------------------------------------------
// Phase A: per-prediction nearest-GT, sort keys, sem one-hot, closs/semloss
// grid (16, 8), 128 threads: thread = one prediction, loops all 1024 GT pts
// ---------------------------------------------------------------------------
__global__ __launch_bounds__(128) void phaseA(
    const float* __restrict__ positions,   // (B, N, 2)
    const float* __restrict__ semantics,   // (B, 3, N)
    const float* __restrict__ gt_pts,      // (B, G, 2)
    const int*   __restrict__ gt_ins,      // (B, G)
    const int*   __restrict__ gt_order,    // (B, G)
    const int*   __restrict__ gt_type,     // (B, G)
    float* __restrict__ out)
{
    const int b = blockIdx.x;
    const int chunk = blockIdx.y;
    const int tid = threadIdx.x;

    __shared__ float2 pgt[NGT];

    // pgt = (gt + BOUND) / (2*BOUND); BOUND == {30.f, 15.f} exactly in f32
    const float* gp = gt_pts + (size_t)b * NGT * 2;
    for (int j = tid; j < NGT; j += 128) {
        float gx = __fdiv_rn(__fadd_rn(gp[2 * j + 0], 30.0f), 60.0f);
        float gy = __fdiv_rn(__fadd_rn(gp[2 * j + 1], 15.0f), 30.0f);
        pgt[j] = make_float2(gx, gy);
    }
    __syncthreads();

    const int p = chunk * 128 + tid;
    const float px = __fdiv_rn(positions[((size_t)b * NPRED + p) * 2 + 0], 399.0f);
    const float py = __fdiv_rn(positions[((size_t)b * NPRED + p) * 2 + 1], 199.0f);

    // 4 independent accumulators (breaks loop-carried FSETP chain), strict '<'
    // preserves first-occurrence within each stride class.
    float dm0 = CUDART_INF_F, dm1 = CUDART_INF_F, dm2 = CUDART_INF_F, dm3 = CUDART_INF_F;
    int   am0 = 0, am1 = 0, am2 = 0, am3 = 0;

    #pragma unroll 2
    for (int j = 0; j < NGT; j += 4) {
        float2 g0 = pgt[j + 0]; float2 g1 = pgt[j + 1];
        float2 g2 = pgt[j + 2]; float2 g3 = pgt[j + 3];
        float dx, dy, d2;
        dx = __fadd_rn(px, -g0.x); dy = __fadd_rn(py, -g0.y);
        d2 = __fadd_rn(__fmul_rn(dx, dx), __fmul_rn(dy, dy));
        if (d2 < dm0) { dm0 = d2; am0 = j + 0; }
        dx = __fadd_rn(px, -g1.x); dy = __fadd_rn(py, -g1.y);
        d2 = __fadd_rn(__fmul_rn(dx, dx), __fmul_rn(dy, dy));
        if (d2 < dm1) { dm1 = d2; am1 = j + 1; }
        dx = __fadd_rn(px, -g2.x); dy = __fadd_rn(py, -g2.y);
        d2 = __fadd_rn(__fmul_rn(dx, dx), __fmul_rn(dy, dy));
        if (d2 < dm2) { dm2 = d2; am2 = j + 2; }
        dx = __fadd_rn(px, -g3.x); dy = __fadd_rn(py, -g3.y);
        d2 = __fadd_rn(__fmul_rn(dx, dx), __fmul_rn(dy, dy));
        if (d2 < dm3) { dm3 = d2; am3 = j + 3; }
    }
    // merge with first-index tie-break (matches jnp.argmin first-occurrence)
    float dmin = dm0; int amin = am0;
    if (dm1 < dmin || (dm1 == dmin && am1 < amin)) { dmin = dm1; amin = am1; }
    if (dm2 < dmin || (dm2 == dmin && am2 < amin)) { dmin = dm2; amin = am2; }
    if (dm3 < dmin || (dm3 == dmin && am3 < amin)) { dmin = dm3; amin = am3; }

    // threshold: replicate numpy f32 chain for CDIST_THR exactly
    const float t0 = 1.5f / 60.0f;
    const float t1 = 1.5f / 30.0f;
    const float thr = sqrtf(__fadd_rn(__fmul_rn(t0, t0), __fmul_rn(t1, t1)));
    const float ndist = sqrtf(__fadd_rn(dmin, 1e-12f));
    const bool valid = ndist < thr;

    const int gi = gt_ins  [(size_t)b * NGT + amin];
    const int go = gt_order[(size_t)b * NGT + amin];
    const int gc = gt_type [(size_t)b * NGT + amin];

    // sort key: (ins+1)[6b] | order[5b] | idx[10b]; ins=-1 -> 0 group
    uint32_t key = ((uint32_t)(valid ? (gi + 1) : 0) << 15) |
                   ((uint32_t)go << 10) | (uint32_t)p;
    g_keys[b * NPRED + p] = key;

    // semantics_gt one-hot (rest is zero via memset)
    out[SG_BASE + (size_t)b * NCLS * NPRED + (size_t)gc * NPRED + p] = 1.0f;

    // partial losses
    float2 gn = pgt[amin];
    float cl = fabsf(__fadd_rn(px, -gn.x)) + fabsf(__fadd_rn(py, -gn.y));
    float sl = semantics[(size_t)b * NCLS * NPRED + (size_t)gc * NPRED + p];

    // deterministic block reduce (128 thr = 4 warps)
    const int lane = tid & 31, warp = tid >> 5;
    #pragma unroll
    for (int o = 16; o > 0; o >>= 1) {
        cl += __shfl_down_sync(0xFFFFFFFFu, cl, o);
        sl += __shfl_down_sync(0xFFFFFFFFu, sl, o);
    }
    __shared__ float rc[4], rs[4];
    if (lane == 0) { rc[warp] = cl; rs[warp] = sl; }
    __syncthreads();
    if (tid == 0) {
        float c = rc[0] + rc[1] + rc[2] + rc[3];
        float s = rs[0] + rs[1] + rs[2] + rs[3];
        g_closs[b * 8 + chunk] = c;
        g_semloss[b * 8 + chunk] = s;
    }
}

// ---------------------------------------------------------------------------
// Phase B: per-sample bitonic sort of keys, build chain edges, scatter M,
// gather match values for mloss. grid 16, 1024 threads.
// ---------------------------------------------------------------------------
__global__ __launch_bounds__(1024) void phaseB(
    const float* __restrict__ matches,     // (B, 1025, 1025)
    float* __restrict__ out)
{
    const int b = blockIdx.x;
    const int i = threadIdx.x;

    __shared__ uint32_t s[NPRED];
    __shared__ unsigned short tf[NPRED], tb[NPRED];
    __shared__ float red[32];

    s[i] = g_keys[b * NPRED + i];
    tf[i] = NPRED;   // default "no edge" -> column/row n
    tb[i] = NPRED;
    __syncthreads();

    // bitonic sort, ascending (keys unique -> stability irrelevant)
    for (unsigned k = 2; k <= NPRED; k <<= 1) {
        for (unsigned j = k >> 1; j > 0; j >>= 1) {
            unsigned ixj = i ^ j;
            if (ixj > (unsigned)i) {
                uint32_t a = s[i], c = s[ixj];
                bool up = ((i & k) == 0);
                if ((a > c) == up) { s[i] = c; s[ixj] = a; }
            }
            __syncthreads();
        }
    }

    // chain edges between consecutive sorted entries with same ins (>=0)
    if (i < NPRED - 1) {
        uint32_t ka = s[i], kb = s[i + 1];
        uint32_t ga = ka >> 15, gb = kb >> 15;
        if (ga == gb && ga != 0) {
            int a = (int)(ka & 1023), c = (int)(kb & 1023);
            tf[a] = (unsigned short)c;   // a -> c (unique a's: no race)
            tb[c] = (unsigned short)a;   // unique c's: no race
        }
    }
    __syncthreads();

    const int f  = tf[i];
    const int bk = tb[i];
    const size_t mrow = (size_t)b * NP1 * NP1 + (size_t)i * NP1;

    // M[i][t_fwd[i]] = 1 (covers both chain edge and end-token column)
    out[M_BASE + mrow + f] = 1.0f;
    // M[n][j] = 1 iff column j has no incoming edge
    if (bk == NPRED)
        out[M_BASE + (size_t)b * NP1 * NP1 + (size_t)NPRED * NP1 + i] = 1.0f;

    // mloss gathers: match[j, t_fwd[j]] + match[j, t_back[j]]
    const size_t inrow = (size_t)b * NP1 * NP1 + (size_t)i * NP1;
    float mv = matches[inrow + f] + matches[inrow + bk];

    // deterministic block reduce over 1024 threads
    const int lane = i & 31, warp = i >> 5;
    #pragma unroll
    for (int o = 16; o > 0; o >>= 1)
        mv += __shfl_down_sync(0xFFFFFFFFu, mv, o);
    if (lane == 0) red[warp] = mv;
    __syncthreads();
    if (i < 32) {
        float x = red[i];
        #pragma unroll
        for (int o = 16; o > 0; o >>= 1)
            x += __shfl_down_sync(0xFFFFFFFFu, x, o);
        if (i == 0) g_mloss[b] = x;
    }
}

// ---------------------------------------------------------------------------
// Phase C: final scalar reduction, fixed order (deterministic)
// ---------------------------------------------------------------------------
__global__ void phaseC(float* __restrict__ out)
{
    if (threadIdx.x == 0) {
        float cs = 0.0f, ss = 0.0f, ms = 0.0f;
        for (int k = 0; k < BATCH * 8; k++) { cs += g_closs[k]; ss += g_semloss[k]; }
        for (int k = 0; k < BATCH; k++) ms += g_mloss[k];
        out[0] = cs / (float)(BATCH * NPRED * 2);     // mean over B of mean(|.|, (N,2))
        out[1] = -ms / (float)(BATCH * NPRED);        // mean over B of -(sum_f+sum_b)/N
        out[2] = -ss / (float)(BATCH * NPRED);        // mean over B of -sum/N
    }
}

extern "C" void kernel_launch(void* const* d_in, const int* in_sizes, int n_in,
                              void* d_out, int out_size)
{
    const float* matches   = (const float*)d_in[0];
    const float* positions = (const float*)d_in[1];
    const float* semantics = (const float*)d_in[2];
    // d_in[3] = masks (all ones, unused by the math)
    const float* gt_pts    = (const float*)d_in[4];
    const int*   gt_ins    = (const int*)  d_in[5];
    const int*   gt_order  = (const int*)  d_in[6];
    const int*   gt_type   = (const int*)  d_in[7];
    float* out = (float*)d_out;

    cudaMemsetAsync(d_out, 0, (size_t)out_size * sizeof(float));

    phaseA<<<dim3(BATCH, 8), 128>>>(positions, semantics, gt_pts,
                                    gt_ins, gt_order, gt_type, out);
    phaseB<<<BATCH, NPRED>>>(matches, out);
    phaseC<<<1, 32>>>(out);
}

// round 2
// speedup vs baseline: 1.1170x; 1.1170x over previous
#include <cuda_runtime.h>
#include <cstdint>
#include <math_constants.h>

#define BATCH 16
#define NPRED 1024
#define NGT   1024
#define NP1   1025
#define NCLS  3

// Output layout (float32): [0..3)=scalars, M region, SG region
#define M_BASE   3
#define M_COUNT  (BATCH * NP1 * NP1)            // 16,810,000 floats
#define SG_BASE  (M_BASE + M_COUNT)
// float4 interior of M region: [4, 4 + 4*INTERIOR4), plus head idx 3 and 3-float tail
#define INTERIOR4   ((M_COUNT - 1) / 4)          // 4,202,499
#define TAIL_START  (4 + 4 * INTERIOR4)          // 16,810,000

__device__ uint32_t g_keys[BATCH * NPRED];
__device__ float g_closs[BATCH * 16];
__device__ float g_semloss[BATCH * 16];
__device__ float g_mloss[BATCH];

// ---------------------------------------------------------------------------
// fusedA: zero-fill M region + per-prediction nearest-GT + keys + SG + losses
// grid (16 samples, 16 segs), 256 threads = 64 preds x 4 GT-chunks of 256
// ---------------------------------------------------------------------------
__global__ __launch_bounds__(256) void fusedA(
    const float* __restrict__ positions,   // (B, N, 2)
    const float* __restrict__ semantics,   // (B, 3, N)
    const float* __restrict__ gt_pts,      // (B, G, 2)
    const int*   __restrict__ gt_ins,      // (B, G)
    const int*   __restrict__ gt_order,    // (B, G)
    const int*   __restrict__ gt_type,     // (B, G)
    float* __restrict__ out)
{
    const int b   = blockIdx.x;
    const int seg = blockIdx.y;
    const int tid = threadIdx.x;
    const int pl  = tid & 63;      // local pred
    const int c   = tid >> 6;      // GT chunk 0..3

    __shared__ float2 pgt[NGT];
    __shared__ float  sdm[256];
    __shared__ int    sam[256];
    __shared__ float  rc2[2], rs2[2];

    // pgt = (gt + BOUND) / (2*BOUND); BOUND == {30.f, 15.f} exactly in f32
    const float* gp = gt_pts + (size_t)b * NGT * 2;
    for (int j = tid; j < NGT; j += 256) {
        float gx = __fdiv_rn(__fadd_rn(gp[2 * j + 0], 30.0f), 60.0f);
        float gy = __fdiv_rn(__fadd_rn(gp[2 * j + 1], 15.0f), 30.0f);
        pgt[j] = make_float2(gx, gy);
    }

    // ---- zero-fill M region (fire-and-forget, overlaps compute drain) ----
    {
        const int gid = (seg * 16 + b) * 256 + tid;   // 0..65535
        const float4 z4 = make_float4(0.f, 0.f, 0.f, 0.f);
        float4* o4 = reinterpret_cast<float4*>(out + 4);
        for (int i = gid; i < INTERIOR4; i += 65536) o4[i] = z4;
        if (gid == 0) {
            out[3] = 0.0f;
            out[TAIL_START + 0] = 0.0f;
            out[TAIL_START + 1] = 0.0f;
            out[TAIL_START + 2] = 0.0f;
        }
    }
    __syncthreads();

    // ---- nearest-GT over this thread's chunk [c*256, c*256+256) ----
    const int p = seg * 64 + pl;
    const float2 pin = reinterpret_cast<const float2*>(positions)[(size_t)b * NPRED + p];
    const float px = __fdiv_rn(pin.x, 399.0f);
    const float py = __fdiv_rn(pin.y, 199.0f);

    const int j0 = c * 256;
    float dm0 = CUDART_INF_F, dm1 = CUDART_INF_F, dm2 = CUDART_INF_F, dm3 = CUDART_INF_F;
    int   am0 = j0, am1 = j0 + 1, am2 = j0 + 2, am3 = j0 + 3;

    #pragma unroll 4
    for (int j = j0; j < j0 + 256; j += 4) {
        float2 g0 = pgt[j + 0]; float2 g1 = pgt[j + 1];
        float2 g2 = pgt[j + 2]; float2 g3 = pgt[j + 3];
        float dx, dy, d2;
        dx = __fadd_rn(px, -g0.x); dy = __fadd_rn(py, -g0.y);
        d2 = __fadd_rn(__fmul_rn(dx, dx), __fmul_rn(dy, dy));
        if (d2 < dm0) { dm0 = d2; am0 = j + 0; }
        dx = __fadd_rn(px, -g1.x); dy = __fadd_rn(py, -g1.y);
        d2 = __fadd_rn(__fmul_rn(dx, dx), __fmul_rn(dy, dy));
        if (d2 < dm1) { dm1 = d2; am1 = j + 1; }
        dx = __fadd_rn(px, -g2.x); dy = __fadd_rn(py, -g2.y);
        d2 = __fadd_rn(__fmul_rn(dx, dx), __fmul_rn(dy, dy));
        if (d2 < dm2) { dm2 = d2; am2 = j + 2; }
        dx = __fadd_rn(px, -g3.x); dy = __fadd_rn(py, -g3.y);
        d2 = __fadd_rn(__fmul_rn(dx, dx), __fmul_rn(dy, dy));
        if (d2 < dm3) { dm3 = d2; am3 = j + 3; }
    }
    // merge 4 stride accumulators, first-occurrence tie-break
    float dmin = dm0; int amin = am0;
    if (dm1 < dmin || (dm1 == dmin && am1 < amin)) { dmin = dm1; amin = am1; }
    if (dm2 < dmin || (dm2 == dmin && am2 < amin)) { dmin = dm2; amin = am2; }
    if (dm3 < dmin || (dm3 == dmin && am3 < amin)) { dmin = dm3; amin = am3; }

    sdm[tid] = dmin;
    sam[tid] = amin;
    __syncthreads();

    if (c == 0) {   // tid < 64: one thread per prediction finishes the job
        #pragma unroll
        for (int cc = 1; cc < 4; cc++) {
            float d = sdm[cc * 64 + pl];
            int   a = sam[cc * 64 + pl];
            if (d < dmin || (d == dmin && a < amin)) { dmin = d; amin = a; }
        }

        // threshold: replicate numpy f32 chain for CDIST_THR exactly
        const float t0 = 1.5f / 60.0f;
        const float t1 = 1.5f / 30.0f;
        const float thr = sqrtf(__fadd_rn(__fmul_rn(t0, t0), __fmul_rn(t1, t1)));
        const float ndist = sqrtf(__fadd_rn(dmin, 1e-12f));
        const bool valid = ndist < thr;

        const int gi = gt_ins  [(size_t)b * NGT + amin];
        const int go = gt_order[(size_t)b * NGT + amin];
        const int gc = gt_type [(size_t)b * NGT + amin];

        // sort key: (ins+1)[6b] | order[5b] | idx[10b]
        g_keys[b * NPRED + p] = ((uint32_t)(valid ? (gi + 1) : 0) << 15) |
                                ((uint32_t)go << 10) | (uint32_t)p;

        // semantics_gt: write all 3 classes directly (no pre-zero needed)
        float* sg = out + SG_BASE + (size_t)b * NCLS * NPRED + p;
        sg[0 * NPRED] = (gc == 0) ? 1.0f : 0.0f;
        sg[1 * NPRED] = (gc == 1) ? 1.0f : 0.0f;
        sg[2 * NPRED] = (gc == 2) ? 1.0f : 0.0f;

        // partial losses
        float2 gn = pgt[amin];
        float cl = fabsf(__fadd_rn(px, -gn.x)) + fabsf(__fadd_rn(py, -gn.y));
        float sl = semantics[(size_t)b * NCLS * NPRED + (size_t)gc * NPRED + p];

        // reduce over 64 threads = 2 warps (deterministic)
        const int lane = tid & 31, warp = tid >> 5;   // warp 0 or 1
        #pragma unroll
        for (int o = 16; o > 0; o >>= 1) {
            cl += __shfl_down_sync(0xFFFFFFFFu, cl, o);
            sl += __shfl_down_sync(0xFFFFFFFFu, sl, o);
        }
        if (lane == 0) { rc2[warp] = cl; rs2[warp] = sl; }
        __syncwarp();
        if (tid == 0) {
            // warp 1's write visibility: both warps passed the earlier
            // __syncthreads? No — need a sync. Use syncthreads below.
        }
    }
    __syncthreads();
    if (tid == 0) {
        g_closs  [b * 16 + seg] = rc2[0] + rc2[1];
        g_semloss[b * 16 + seg] = rs2[0] + rs2[1];
    }
}

// ---------------------------------------------------------------------------
// phaseB: per-sample bitonic sort (register + shuffle for j<32, double-buffered
// smem for j>=32), chain edges, scatter M ones, gather match values for mloss.
// grid 16, 1024 threads.
// ---------------------------------------------------------------------------
__global__ __launch_bounds__(1024) void phaseB(
    const float* __restrict__ matches,     // (B, 1025, 1025)
    float* __restrict__ out)
{
    const int b = blockIdx.x;
    const int i = threadIdx.x;

    __shared__ uint32_t buf[2][NPRED];
    __shared__ unsigned short tf[NPRED], tb[NPRED];
    __shared__ float red[32];

    uint32_t v = g_keys[b * NPRED + i];
    tf[i] = NPRED;
    tb[i] = NPRED;

    int cur = 0;
    for (unsigned k = 2; k <= NPRED; k <<= 1) {
        const bool asc = ((i & k) == 0);
        for (unsigned j = k >> 1; j > 0; j >>= 1) {
            uint32_t pv;
            if (j >= 32) {
                buf[cur][i] = v;
                __syncthreads();
                pv = buf[cur][i ^ j];
                cur ^= 1;
            } else {
                pv = __shfl_xor_sync(0xFFFFFFFFu, v, j);
            }
            const bool lower = ((i & j) == 0);
            uint32_t mn = v < pv ? v : pv;
            uint32_t mx = v < pv ? pv : v;
            v = (lower == asc) ? mn : mx;
        }
    }

    // publish sorted keys (safe: last shared step's reads fenced by its sync,
    // and cur now points at the buffer whose readers finished earlier)
    buf[cur][i] = v;
    __syncthreads();

    // chain edges between consecutive sorted entries with same valid ins
    if (i < NPRED - 1) {
        uint32_t ka = buf[cur][i], kb = buf[cur][i + 1];
        uint32_t ga = ka >> 15, gb = kb >> 15;
        if (ga == gb && ga != 0) {
            int a = (int)(ka & 1023), c = (int)(kb & 1023);
            tf[a] = (unsigned short)c;
            tb[c] = (unsigned short)a;
        }
    }
    __syncthreads();

    const int f  = tf[i];
    const int bk = tb[i];
    const size_t mrow = (size_t)b * NP1 * NP1 + (size_t)i * NP1;

    out[M_BASE + mrow + f] = 1.0f;                       // M[i][t_fwd[i]] = 1
    if (bk == NPRED)                                     // M[n][j] = no incoming
        out[M_BASE + (size_t)b * NP1 * NP1 + (size_t)NPRED * NP1 + i] = 1.0f;

    // mloss gathers: match[j, t_fwd[j]] + match[j, t_back[j]]
    float mv = matches[mrow + f] + matches[mrow + bk];

    const int lane = i & 31, warp = i >> 5;
    #pragma unroll
    for (int o = 16; o > 0; o >>= 1)
        mv += __shfl_down_sync(0xFFFFFFFFu, mv, o);
    if (lane == 0) red[warp] = mv;
    __syncthreads();
    if (i < 32) {
        float x = red[i];
        #pragma unroll
        for (int o = 16; o > 0; o >>= 1)
            x += __shfl_down_sync(0xFFFFFFFFu, x, o);
        if (i == 0) g_mloss[b] = x;
    }
}

// ---------------------------------------------------------------------------
// phaseC: final scalar reduction, fixed order (deterministic)
// ---------------------------------------------------------------------------
__global__ void phaseC(float* __restrict__ out)
{
    if (threadIdx.x == 0) {
        float cs = 0.0f, ss = 0.0f, ms = 0.0f;
        for (int k = 0; k < BATCH * 16; k++) { cs += g_closs[k]; ss += g_semloss[k]; }
        for (int k = 0; k < BATCH; k++) ms += g_mloss[k];
        out[0] = cs / (float)(BATCH * NPRED * 2);
        out[1] = -ms / (float)(BATCH * NPRED);
        out[2] = -ss / (float)(BATCH * NPRED);
    }
}

extern "C" void kernel_launch(void* const* d_in, const int* in_sizes, int n_in,
                              void* d_out, int out_size)
{
    const float* matches   = (const float*)d_in[0];
    const float* positions = (const float*)d_in[1];
    const float* semantics = (const float*)d_in[2];
    // d_in[3] = masks (all ones, unused by the math)
    const float* gt_pts    = (const float*)d_in[4];
    const int*   gt_ins    = (const int*)  d_in[5];
    const int*   gt_order  = (const int*)  d_in[6];
    const int*   gt_type   = (const int*)  d_in[7];
    float* out = (float*)d_out;

    fusedA<<<dim3(BATCH, 16), 256>>>(positions, semantics, gt_pts,
                                     gt_ins, gt_order, gt_type, out);
    phaseB<<<BATCH, NPRED>>>(matches, out);
    phaseC<<<1, 32>>>(out);
}